// round 11
// baseline (speedup 1.0000x reference)
#include <cuda_runtime.h>
#include <cstdint>

#define BS 32
#define NANCH 90000
#define NVEC (NANCH / 4)       // 22500 float4 per batch
#define NQ 8                   // slices per batch
#define QVEC 2816              // ceil(22500/8); last slice clipped
#define KPRE 1000
#define KPOST 300
#define NWORDS 16              // 16*64 = 1024 >= 1000
#define NMS_THR 0.7f
#define NMB 4                  // mask blocks per batch in fused NMS kernel

#define HBITS 13
#define NBINS (1 << HBITS)     // 8192
#define HSHIFT (32 - HBITS)    // 19
#define QCAP 4096
#define CANDCAP 4096

typedef unsigned long long u64;

// ---------------- scratch (static device globals; no allocation) ----------------
__device__ unsigned g_hist4[BS][NQ][NBINS];            // overwritten each run
__device__ unsigned g_qcnt[BS][NQ];
__device__ u64      g_qcand[BS][NQ][QCAP];
__device__ unsigned g_sync[BS];                        // K1 election counters
__device__ unsigned g_sync2[BS];                       // NMS election counters
__device__ float4   g_boxes[BS][KPRE];
__device__ float    g_scores[BS][KPRE];
__device__ __align__(128) u64 g_mask[BS][KPRE][NWORDS]; // lower-tri never written (stays 0)

__device__ const int c_cbtbl[NMB][4] = {
    {0, 15, 7, 8}, {1, 14, 6, 9}, {2, 13, 5, 10}, {3, 12, 4, 11}
};

// float -> order-preserving uint (ascending)
__device__ __forceinline__ unsigned flip_f(float f) {
    unsigned u = __float_as_uint(f);
    return (u & 0x80000000u) ? ~u : (u | 0x80000000u);
}
__device__ __forceinline__ float unflip_f(unsigned k) {
    unsigned u = (k & 0x80000000u) ? (k ^ 0x80000000u) : ~k;
    return __uint_as_float(u);
}
__device__ __forceinline__ float read_dim(const int* p) {
    int v = *p;
    if (v > 0 && v < (1 << 24)) return (float)v;
    return __int_as_float(v);
}

// Warp/CTA suffix-threshold: given smem hist, find largest bin t with
// suffix_count(t) >= KPRE. 1024 threads, 8 bins/thread, 2 full barriers.
__device__ __forceinline__ void find_threshold(
    const unsigned* hist, unsigned* s_wsum, unsigned* s_wafter, unsigned* s_t,
    int tid)
{
    const int lane = tid & 31;
    const int wrp  = tid >> 5;
    const int base = tid * (NBINS / 1024);     // 8 bins
    unsigned s = 0;
    #pragma unroll
    for (int k = 0; k < NBINS / 1024; ++k) s += hist[base + k];

    // intra-warp inclusive suffix
    unsigned val = s;
    #pragma unroll
    for (int off = 1; off < 32; off <<= 1) {
        unsigned v = __shfl_down_sync(0xFFFFFFFFu, val, off);
        if (lane + off < 32) val += v;
    }
    if (lane == 0) s_wsum[wrp] = val;          // warp total
    __syncthreads();

    if (wrp == 0) {
        unsigned t0 = s_wsum[lane];
        unsigned v0 = t0;
        #pragma unroll
        for (int off = 1; off < 32; off <<= 1) {
            unsigned v = __shfl_down_sync(0xFFFFFFFFu, v0, off);
            if (lane + off < 32) v0 += v;
        }
        s_wafter[lane] = v0 - t0;              // suffix strictly after warp
    }
    __syncthreads();

    unsigned mine  = val + s_wafter[wrp];      // suffix including my bins
    unsigned above = mine - s;                 // suffix after my bins
    if (mine >= KPRE && above < KPRE) {
        unsigned acc = above;
        int t = base;
        #pragma unroll
        for (int k = NBINS / 1024 - 1; k >= 0; --k) {
            acc += hist[base + k];
            if (acc >= KPRE) { t = base + k; break; }
        }
        *s_t = (unsigned)t;
    }
}

// =============================================================================
// K1: per-slice histogram + local gather; last slice-CTA of each batch elected
// to do global select (sum slices -> threshold -> filter -> sort -> decode).
// grid (NQ, BS), 1024 threads, 32 KB dynamic smem.
// =============================================================================
extern __shared__ unsigned s_dynA[];

__global__ __launch_bounds__(1024, 2) void select_fused_kernel(
    const float* __restrict__ logits,
    const float* __restrict__ deltas,
    const float* __restrict__ anchors,
    const int* __restrict__ p_ih,
    const int* __restrict__ p_iw)
{
    const int b   = blockIdx.y;
    const int q   = blockIdx.x;
    const int tid = threadIdx.x;

    unsigned* hist = s_dynA;                 // NBINS u32 (32 KB)
    u64*      cand = (u64*)s_dynA;           // CANDCAP u64 (32 KB), aliased later
    __shared__ unsigned s_wsum[32];
    __shared__ unsigned s_wafter[32];
    __shared__ unsigned s_t;
    __shared__ unsigned s_cnt;
    __shared__ int s_last;

    const float4* lg4 = (const float4*)(logits + (size_t)b * NANCH);
    const int v0 = q * QVEC;
    const int v1 = min(v0 + QVEC, NVEC);

    for (int i = tid; i < NBINS; i += 1024) hist[i] = 0u;
    if (tid == 0) s_cnt = 0u;
    __syncthreads();

    // ---- sweep 1: histogram ----
    for (int i = v0 + tid; i < v1; i += 1024) {
        float4 v = lg4[i];
        atomicAdd(&hist[flip_f(v.x) >> HSHIFT], 1u);
        atomicAdd(&hist[flip_f(v.y) >> HSHIFT], 1u);
        atomicAdd(&hist[flip_f(v.z) >> HSHIFT], 1u);
        atomicAdd(&hist[flip_f(v.w) >> HSHIFT], 1u);
    }
    __syncthreads();

    // ---- write hist slice ----
    for (int i = tid; i < NBINS; i += 1024) g_hist4[b][q][i] = hist[i];

    // ---- local threshold ----
    find_threshold(hist, s_wsum, s_wafter, &s_t, tid);
    __syncthreads();
    const unsigned tq = s_t;

    // ---- sweep 2: gather local candidates ----
    for (int i = v0 + tid; i < v1; i += 1024) {
        float4 v = lg4[i];
        unsigned k0 = flip_f(v.x);
        unsigned k1 = flip_f(v.y);
        unsigned k2 = flip_f(v.z);
        unsigned k3 = flip_f(v.w);
        const int i0 = 4 * i;
        if ((k0 >> HSHIFT) >= tq) {
            unsigned p = atomicAdd(&s_cnt, 1u);
            if (p < QCAP) g_qcand[b][q][p] = ((u64)k0 << 32) | (unsigned)(~(unsigned)(i0));
        }
        if ((k1 >> HSHIFT) >= tq) {
            unsigned p = atomicAdd(&s_cnt, 1u);
            if (p < QCAP) g_qcand[b][q][p] = ((u64)k1 << 32) | (unsigned)(~(unsigned)(i0 + 1));
        }
        if ((k2 >> HSHIFT) >= tq) {
            unsigned p = atomicAdd(&s_cnt, 1u);
            if (p < QCAP) g_qcand[b][q][p] = ((u64)k2 << 32) | (unsigned)(~(unsigned)(i0 + 2));
        }
        if ((k3 >> HSHIFT) >= tq) {
            unsigned p = atomicAdd(&s_cnt, 1u);
            if (p < QCAP) g_qcand[b][q][p] = ((u64)k3 << 32) | (unsigned)(~(unsigned)(i0 + 3));
        }
    }
    __syncthreads();
    if (tid == 0) {
        g_qcnt[b][q] = min(s_cnt, (unsigned)QCAP);
        __threadfence();
        unsigned old = atomicAdd(&g_sync[b], 1u);
        s_last = (old == NQ - 1);
        if (s_last) g_sync[b] = 0u;
    }
    __syncthreads();
    if (!s_last) return;

    // =================== global select (elected CTA only) ===================
    __threadfence();
    if (tid == 0) s_cnt = 0u;

    for (int i = tid; i < NBINS; i += 1024) {
        unsigned s = 0;
        #pragma unroll
        for (int qq = 0; qq < NQ; ++qq) s += g_hist4[b][qq][i];
        hist[i] = s;
    }
    __syncthreads();

    find_threshold(hist, s_wsum, s_wafter, &s_t, tid);
    __syncthreads();
    const unsigned t = s_t;
    __syncthreads();            // all hist reads done before aliasing to cand

    #pragma unroll
    for (int qq = 0; qq < NQ; ++qq) {
        const int nq = (int)g_qcnt[b][qq];
        for (int i = tid; i < nq; i += 1024) {
            u64 comp = g_qcand[b][qq][i];
            if (((unsigned)(comp >> 32) >> HSHIFT) >= t) {
                unsigned p = atomicAdd(&s_cnt, 1u);
                if (p < CANDCAP) cand[p] = comp;
            }
        }
    }
    __syncthreads();

    const int n = min((int)s_cnt, CANDCAP);
    const int S = (n <= 2048) ? 2048 : CANDCAP;
    for (int i = n + tid; i < S; i += 1024) cand[i] = 0ull;

    // ---- bitonic sort desc; full barrier only for cross-warp strides ----
    int prev_big = 1;
    for (int size = 2; size <= S; size <<= 1) {
        for (int stride = size >> 1; stride > 0; stride >>= 1) {
            const int big = (stride >= 32);
            if (big || prev_big) __syncthreads(); else __syncwarp();
            for (int k = tid; k < (S >> 1); k += 1024) {
                int i = 2 * k - (k & (stride - 1));
                int j = i + stride;
                u64 a = cand[i];
                u64 c = cand[j];
                bool desc = ((i & size) == 0);
                if ((a < c) == desc) { cand[i] = c; cand[j] = a; }
            }
            prev_big = big;
        }
    }
    __syncthreads();

    // ---- decode + clip top-1000 ----
    const float fw = read_dim(p_iw);
    const float fh = read_dim(p_ih);
    if (tid < KPRE) {
        u64 comp = cand[tid];
        unsigned idx = ~(unsigned)(comp & 0xFFFFFFFFull);
        unsigned key = (unsigned)(comp >> 32);
        float logit = unflip_f(key);
        float score = 1.0f / (1.0f + expf(-logit));

        float4 d = ((const float4*)deltas)[(size_t)b * NANCH + idx];
        float4 a = ((const float4*)anchors)[idx];
        float aw  = a.z - a.x;
        float ah  = a.w - a.y;
        float acx = a.x + 0.5f * aw;
        float acy = a.y + 0.5f * ah;
        float cx = d.x * aw + acx;
        float cy = d.y * ah + acy;
        float w  = expf(d.z) * aw;
        float h  = expf(d.w) * ah;
        float x1 = fminf(fmaxf(cx - 0.5f * w, 0.0f), fw);
        float y1 = fminf(fmaxf(cy - 0.5f * h, 0.0f), fh);
        float x2 = fminf(fmaxf(cx + 0.5f * w, 0.0f), fw);
        float y2 = fminf(fmaxf(cy + 0.5f * h, 0.0f), fh);
        g_boxes[b][tid]  = make_float4(x1, y1, x2, y2);
        g_scores[b][tid] = score;
    }
}

// =============================================================================
// K2+K3 fused: grid (NMB, BS), 1024 threads, 128 KB dynamic smem.
// Each block computes 4 column-stripes of the IoU mask (balanced by triangle
// weight); the last block per batch (election) preloads the mask and runs the
// serial greedy scan + output.
// =============================================================================
extern __shared__ u64 s_mask2[];   // KPRE*NWORDS u64 = 128 KB (elected only)

__global__ __launch_bounds__(1024) void nms_fused_kernel(float* __restrict__ out)
{
    const int b   = blockIdx.y;
    const int mb  = blockIdx.x;
    const int tid = threadIdx.x;

    __shared__ float4 cbox[64];
    __shared__ float  carea[64];
    __shared__ int s_list[KPOST];
    __shared__ int s_kept;
    __shared__ int s_last;

    // ---- mask phase: 4 column-blocks per block ----
    float4 bi;
    float  ai = 0.0f;
    const bool rowok = (tid < KPRE);
    if (rowok) {
        bi = g_boxes[b][tid];
        ai = (bi.z - bi.x) * (bi.w - bi.y);
    }

    #pragma unroll
    for (int c = 0; c < 4; ++c) {
        const int cb    = c_cbtbl[mb][c];
        const int cbase = cb * 64;
        const int ncol  = min(64, KPRE - cbase);
        __syncthreads();                    // protect cbox reuse
        if (tid < ncol) {
            float4 bx = g_boxes[b][cbase + tid];
            cbox[tid]  = bx;
            carea[tid] = (bx.z - bx.x) * (bx.w - bx.y);
        }
        __syncthreads();

        if (rowok && cb >= (tid >> 6)) {
            u64 bits = 0ull;
            const int j0 = (tid >= cbase) ? (tid - cbase + 1) : 0;
            for (int j = j0; j < ncol; ++j) {
                float4 bj = cbox[j];
                float lx = fmaxf(bi.x, bj.x);
                float ly = fmaxf(bi.y, bj.y);
                float rx = fminf(bi.z, bj.z);
                float ry = fminf(bi.w, bj.w);
                float w  = fmaxf(rx - lx, 0.0f);
                float h  = fmaxf(ry - ly, 0.0f);
                float inter = w * h;
                float u = ai + carea[j] - inter + 1e-12f;
                float d = inter - NMS_THR * u;
                bool sup = d > 0.0f;
                if (fabsf(d) <= 1e-4f * u)
                    sup = (inter / u) > NMS_THR;
                if (sup) bits |= (1ull << j);
            }
            g_mask[b][tid][cb] = bits;
        }
    }
    __syncthreads();

    // ---- election: last mask block of this batch continues ----
    if (tid == 0) {
        __threadfence();
        unsigned old = atomicAdd(&g_sync2[b], 1u);
        s_last = (old == NMB - 1);
        if (s_last) g_sync2[b] = 0u;
    }
    __syncthreads();
    if (!s_last) return;
    __threadfence();

    // ---- preload full mask into shared ----
    const ulonglong2* gm2 = (const ulonglong2*)&g_mask[b][0][0];
    ulonglong2* sm2 = (ulonglong2*)s_mask2;
    for (int i = tid; i < KPRE * NWORDS / 2; i += 1024) sm2[i] = gm2[i];
    __syncthreads();

    // ---- serial greedy scan (R7 + Duff trimmed OR) ----
    if (tid == 0) {
        u64 remv[NWORDS];
        #pragma unroll
        for (int k = 0; k < NWORDS; ++k) remv[k] = 0ull;
        int kept = 0;
        #pragma unroll
        for (int w = 0; w < NWORDS; ++w) {
            if (kept >= KPOST) break;
            const u64 valid = (w == NWORDS - 1)
                ? ((1ull << (KPRE - 64 * (NWORDS - 1))) - 1ull) : ~0ull;
            u64 avail = (~remv[w]) & valid;
            while (avail) {
                int bit = __ffsll((long long)avail) - 1;
                int i = w * 64 + bit;
                s_list[kept++] = i;
                if (kept == KPOST) break;
                const ulonglong2* row = (const ulonglong2*)&s_mask2[i * NWORDS];
                switch (w >> 1) {
                case 0: { ulonglong2 v = row[0]; remv[0]  |= v.x; remv[1]  |= v.y; }
                case 1: { ulonglong2 v = row[1]; remv[2]  |= v.x; remv[3]  |= v.y; }
                case 2: { ulonglong2 v = row[2]; remv[4]  |= v.x; remv[5]  |= v.y; }
                case 3: { ulonglong2 v = row[3]; remv[6]  |= v.x; remv[7]  |= v.y; }
                case 4: { ulonglong2 v = row[4]; remv[8]  |= v.x; remv[9]  |= v.y; }
                case 5: { ulonglong2 v = row[5]; remv[10] |= v.x; remv[11] |= v.y; }
                case 6: { ulonglong2 v = row[6]; remv[12] |= v.x; remv[13] |= v.y; }
                case 7: { ulonglong2 v = row[7]; remv[14] |= v.x; remv[15] |= v.y; }
                }
                u64 high = (bit == 63) ? 0ull : (~0ull << (bit + 1));
                avail = (~remv[w]) & valid & high;
            }
        }
        s_kept = kept;
    }
    __syncthreads();

    // ---- output ----
    const int kept = s_kept;
    float* ob = out + (size_t)b * KPOST * 5;
    for (int r = tid; r < KPOST; r += 1024) {
        if (r < kept) {
            int i = s_list[r];
            float4 bx = g_boxes[b][i];
            float  sc = g_scores[b][i];
            ob[r * 5 + 0] = bx.x;
            ob[r * 5 + 1] = bx.y;
            ob[r * 5 + 2] = bx.z;
            ob[r * 5 + 3] = bx.w;
            ob[r * 5 + 4] = sc;
        } else {
            ob[r * 5 + 0] = 0.0f;
            ob[r * 5 + 1] = 0.0f;
            ob[r * 5 + 2] = 0.0f;
            ob[r * 5 + 3] = 0.0f;
            ob[r * 5 + 4] = 0.0f;
        }
    }
}

// =============================================================================
extern "C" void kernel_launch(void* const* d_in, const int* in_sizes, int n_in,
                              void* d_out, int out_size)
{
    const float* logits  = (const float*)d_in[0];
    const float* deltas  = (const float*)d_in[1];
    const float* anchors = (const float*)d_in[2];
    const int*   p_ih    = (const int*)d_in[3];
    const int*   p_iw    = (const int*)d_in[4];

    cudaFuncSetAttribute(select_fused_kernel,
                         cudaFuncAttributeMaxDynamicSharedMemorySize,
                         CANDCAP * (int)sizeof(u64));     // 32 KB (== NBINS*4)
    cudaFuncSetAttribute(nms_fused_kernel,
                         cudaFuncAttributeMaxDynamicSharedMemorySize,
                         KPRE * NWORDS * (int)sizeof(u64));

    select_fused_kernel<<<dim3(NQ, BS), 1024, CANDCAP * sizeof(u64)>>>(
        logits, deltas, anchors, p_ih, p_iw);
    nms_fused_kernel<<<dim3(NMB, BS), 1024, KPRE * NWORDS * sizeof(u64)>>>(
        (float*)d_out);
}

// round 12
// speedup vs baseline: 1.0608x; 1.0608x over previous
#include <cuda_runtime.h>
#include <cstdint>

#define BS 32
#define NANCH 90000
#define NVEC (NANCH / 4)       // 22500 float4 per batch
#define NQ 8                   // slices per batch
#define QVEC 2816              // ceil(22500/8); last slice clipped
#define KPRE 1000
#define KPOST 300
#define NWORDS 16              // 16*64 = 1024 >= 1000
#define NMS_THR 0.7f

#define HBITS 13
#define NBINS (1 << HBITS)     // 8192
#define HSHIFT (32 - HBITS)    // 19
#define QCAP 4096
#define CANDCAP 4096

typedef unsigned long long u64;

// ---------------- scratch (static device globals; no allocation) ----------------
__device__ unsigned g_hist4[BS][NQ][NBINS];            // overwritten each run
__device__ unsigned g_qcnt[BS][NQ];
__device__ u64      g_qcand[BS][NQ][QCAP];
__device__ unsigned g_sync[BS];                        // K1 election counters
__device__ float4   g_boxes[BS][KPRE];
__device__ float    g_scores[BS][KPRE];
__device__ __align__(128) u64 g_mask[BS][KPRE][NWORDS]; // lower-tri never written (stays 0)

// float -> order-preserving uint (ascending)
__device__ __forceinline__ unsigned flip_f(float f) {
    unsigned u = __float_as_uint(f);
    return (u & 0x80000000u) ? ~u : (u | 0x80000000u);
}
__device__ __forceinline__ float unflip_f(unsigned k) {
    unsigned u = (k & 0x80000000u) ? (k ^ 0x80000000u) : ~k;
    return __uint_as_float(u);
}
__device__ __forceinline__ float read_dim(const int* p) {
    int v = *p;
    if (v > 0 && v < (1 << 24)) return (float)v;
    return __int_as_float(v);
}

// CTA suffix-threshold via warp shfl: largest bin t with suffix(t) >= KPRE.
__device__ __forceinline__ void find_threshold(
    const unsigned* hist, unsigned* s_wsum, unsigned* s_wafter, unsigned* s_t,
    int tid)
{
    const int lane = tid & 31;
    const int wrp  = tid >> 5;
    const int base = tid * (NBINS / 1024);     // 8 bins
    unsigned s = 0;
    #pragma unroll
    for (int k = 0; k < NBINS / 1024; ++k) s += hist[base + k];

    unsigned val = s;
    #pragma unroll
    for (int off = 1; off < 32; off <<= 1) {
        unsigned v = __shfl_down_sync(0xFFFFFFFFu, val, off);
        if (lane + off < 32) val += v;
    }
    if (lane == 0) s_wsum[wrp] = val;
    __syncthreads();

    if (wrp == 0) {
        unsigned t0 = s_wsum[lane];
        unsigned v0 = t0;
        #pragma unroll
        for (int off = 1; off < 32; off <<= 1) {
            unsigned v = __shfl_down_sync(0xFFFFFFFFu, v0, off);
            if (lane + off < 32) v0 += v;
        }
        s_wafter[lane] = v0 - t0;
    }
    __syncthreads();

    unsigned mine  = val + s_wafter[wrp];
    unsigned above = mine - s;
    if (mine >= KPRE && above < KPRE) {
        unsigned acc = above;
        int t = base;
        #pragma unroll
        for (int k = NBINS / 1024 - 1; k >= 0; --k) {
            acc += hist[base + k];
            if (acc >= KPRE) { t = base + k; break; }
        }
        *s_t = (unsigned)t;
    }
}

// =============================================================================
// K1: per-slice histogram + local gather; last slice-CTA per batch elected to
// do global select. grid (NQ, BS), 1024 threads, 32 KB dynamic smem, 2 CTA/SM.
// =============================================================================
extern __shared__ unsigned s_dynA[];

__global__ __launch_bounds__(1024, 2) void select_fused_kernel(
    const float* __restrict__ logits,
    const float* __restrict__ deltas,
    const float* __restrict__ anchors,
    const int* __restrict__ p_ih,
    const int* __restrict__ p_iw)
{
    const int b   = blockIdx.y;
    const int q   = blockIdx.x;
    const int tid = threadIdx.x;

    unsigned* hist = s_dynA;                 // NBINS u32 (32 KB)
    u64*      cand = (u64*)s_dynA;           // CANDCAP u64 (32 KB), aliased later
    __shared__ unsigned s_wsum[32];
    __shared__ unsigned s_wafter[32];
    __shared__ unsigned s_t;
    __shared__ unsigned s_cnt;
    __shared__ int s_last;

    const float4* lg4 = (const float4*)(logits + (size_t)b * NANCH);
    const int v0 = q * QVEC;
    const int v1 = min(v0 + QVEC, NVEC);

    for (int i = tid; i < NBINS; i += 1024) hist[i] = 0u;
    if (tid == 0) s_cnt = 0u;
    __syncthreads();

    // ---- sweep 1: histogram ----
    for (int i = v0 + tid; i < v1; i += 1024) {
        float4 v = lg4[i];
        atomicAdd(&hist[flip_f(v.x) >> HSHIFT], 1u);
        atomicAdd(&hist[flip_f(v.y) >> HSHIFT], 1u);
        atomicAdd(&hist[flip_f(v.z) >> HSHIFT], 1u);
        atomicAdd(&hist[flip_f(v.w) >> HSHIFT], 1u);
    }
    __syncthreads();

    // ---- write hist slice ----
    for (int i = tid; i < NBINS; i += 1024) g_hist4[b][q][i] = hist[i];

    // ---- local threshold ----
    find_threshold(hist, s_wsum, s_wafter, &s_t, tid);
    __syncthreads();
    const unsigned tq = s_t;

    // ---- sweep 2: gather local candidates ----
    for (int i = v0 + tid; i < v1; i += 1024) {
        float4 v = lg4[i];
        unsigned k0 = flip_f(v.x);
        unsigned k1 = flip_f(v.y);
        unsigned k2 = flip_f(v.z);
        unsigned k3 = flip_f(v.w);
        const int i0 = 4 * i;
        if ((k0 >> HSHIFT) >= tq) {
            unsigned p = atomicAdd(&s_cnt, 1u);
            if (p < QCAP) g_qcand[b][q][p] = ((u64)k0 << 32) | (unsigned)(~(unsigned)(i0));
        }
        if ((k1 >> HSHIFT) >= tq) {
            unsigned p = atomicAdd(&s_cnt, 1u);
            if (p < QCAP) g_qcand[b][q][p] = ((u64)k1 << 32) | (unsigned)(~(unsigned)(i0 + 1));
        }
        if ((k2 >> HSHIFT) >= tq) {
            unsigned p = atomicAdd(&s_cnt, 1u);
            if (p < QCAP) g_qcand[b][q][p] = ((u64)k2 << 32) | (unsigned)(~(unsigned)(i0 + 2));
        }
        if ((k3 >> HSHIFT) >= tq) {
            unsigned p = atomicAdd(&s_cnt, 1u);
            if (p < QCAP) g_qcand[b][q][p] = ((u64)k3 << 32) | (unsigned)(~(unsigned)(i0 + 3));
        }
    }
    __syncthreads();
    if (tid == 0) {
        g_qcnt[b][q] = min(s_cnt, (unsigned)QCAP);
        __threadfence();
        unsigned old = atomicAdd(&g_sync[b], 1u);
        s_last = (old == NQ - 1);
        if (s_last) g_sync[b] = 0u;
    }
    __syncthreads();
    if (!s_last) return;

    // =================== global select (elected CTA only) ===================
    __threadfence();
    if (tid == 0) s_cnt = 0u;

    for (int i = tid; i < NBINS; i += 1024) {
        unsigned s = 0;
        #pragma unroll
        for (int qq = 0; qq < NQ; ++qq) s += g_hist4[b][qq][i];
        hist[i] = s;
    }
    __syncthreads();

    find_threshold(hist, s_wsum, s_wafter, &s_t, tid);
    __syncthreads();
    const unsigned t = s_t;
    __syncthreads();            // all hist reads done before aliasing to cand

    #pragma unroll
    for (int qq = 0; qq < NQ; ++qq) {
        const int nq = (int)g_qcnt[b][qq];
        for (int i = tid; i < nq; i += 1024) {
            u64 comp = g_qcand[b][qq][i];
            if (((unsigned)(comp >> 32) >> HSHIFT) >= t) {
                unsigned p = atomicAdd(&s_cnt, 1u);
                if (p < CANDCAP) cand[p] = comp;
            }
        }
    }
    __syncthreads();

    const int n = min((int)s_cnt, CANDCAP);
    const int S = (n <= 2048) ? 2048 : CANDCAP;
    for (int i = n + tid; i < S; i += 1024) cand[i] = 0ull;

    // ---- bitonic sort desc; full barrier only around cross-warp strides ----
    int prev_big = 1;
    for (int size = 2; size <= S; size <<= 1) {
        for (int stride = size >> 1; stride > 0; stride >>= 1) {
            const int big = (stride >= 32);
            if (big || prev_big) __syncthreads(); else __syncwarp();
            for (int k = tid; k < (S >> 1); k += 1024) {
                int i = 2 * k - (k & (stride - 1));
                int j = i + stride;
                u64 a = cand[i];
                u64 c = cand[j];
                bool desc = ((i & size) == 0);
                if ((a < c) == desc) { cand[i] = c; cand[j] = a; }
            }
            prev_big = big;
        }
    }
    __syncthreads();

    // ---- decode + clip top-1000 ----
    const float fw = read_dim(p_iw);
    const float fh = read_dim(p_ih);
    if (tid < KPRE) {
        u64 comp = cand[tid];
        unsigned idx = ~(unsigned)(comp & 0xFFFFFFFFull);
        unsigned key = (unsigned)(comp >> 32);
        float logit = unflip_f(key);
        float score = 1.0f / (1.0f + expf(-logit));

        float4 d = ((const float4*)deltas)[(size_t)b * NANCH + idx];
        float4 a = ((const float4*)anchors)[idx];
        float aw  = a.z - a.x;
        float ah  = a.w - a.y;
        float acx = a.x + 0.5f * aw;
        float acy = a.y + 0.5f * ah;
        float cx = d.x * aw + acx;
        float cy = d.y * ah + acy;
        float w  = expf(d.z) * aw;
        float h  = expf(d.w) * ah;
        float x1 = fminf(fmaxf(cx - 0.5f * w, 0.0f), fw);
        float y1 = fminf(fmaxf(cy - 0.5f * h, 0.0f), fh);
        float x2 = fminf(fmaxf(cx + 0.5f * w, 0.0f), fw);
        float y2 = fminf(fmaxf(cy + 0.5f * h, 0.0f), fh);
        g_boxes[b][tid]  = make_float4(x1, y1, x2, y2);
        g_scores[b][tid] = score;
    }
}

// =============================================================================
// K2: IoU bitmask, upper-triangular blocks, divide-free fast path with exact
//     fallback near the decision boundary. grid (136, BS), 64 threads.
// =============================================================================
__global__ __launch_bounds__(64) void nms_mask_kernel()
{
    const int b = blockIdx.y;
    int p = blockIdx.x;
    int rb = 0, rem = NWORDS;
    while (p >= rem) { p -= rem; ++rb; --rem; }
    const int cb = rb + p;
    const int i  = rb * 64 + threadIdx.x;

    __shared__ float4 cbox[64];
    __shared__ float  carea[64];
    const int cbase = cb * 64;
    const int ncol  = min(64, KPRE - cbase);
    if (threadIdx.x < ncol) {
        float4 bx = g_boxes[b][cbase + threadIdx.x];
        cbox[threadIdx.x]  = bx;
        carea[threadIdx.x] = (bx.z - bx.x) * (bx.w - bx.y);
    }
    __syncthreads();
    if (i >= KPRE) return;

    u64 bits = 0ull;
    float4 bi = g_boxes[b][i];
    float  ai = (bi.z - bi.x) * (bi.w - bi.y);
    const int j0 = (i >= cbase) ? (i - cbase + 1) : 0;
    for (int j = j0; j < ncol; ++j) {
        float4 bj = cbox[j];
        float lx = fmaxf(bi.x, bj.x);
        float ly = fmaxf(bi.y, bj.y);
        float rx = fminf(bi.z, bj.z);
        float ry = fminf(bi.w, bj.w);
        float w  = fmaxf(rx - lx, 0.0f);
        float h  = fmaxf(ry - ly, 0.0f);
        float inter = w * h;
        float u = ai + carea[j] - inter + 1e-12f;
        float d = inter - NMS_THR * u;
        bool sup = d > 0.0f;
        if (fabsf(d) <= 1e-4f * u)
            sup = (inter / u) > NMS_THR;
        if (sup) bits |= (1ull << j);
    }
    g_mask[b][i][cb] = bits;
}

// =============================================================================
// K3: sequential greedy scan (R7 algorithm), register-resident removal mask,
//     LDS.128 row loads, Duff-trimmed OR. grid (BS), 1024 threads, 128 KB smem.
// =============================================================================
extern __shared__ u64 s_mask[];   // KPRE*NWORDS u64 = 128 KB

__global__ __launch_bounds__(1024) void nms_scan_out_kernel(float* __restrict__ out)
{
    const int b   = blockIdx.x;
    const int tid = threadIdx.x;

    __shared__ int s_list[KPOST];
    __shared__ int s_kept;

    const ulonglong2* gm2 = (const ulonglong2*)&g_mask[b][0][0];
    ulonglong2* sm2 = (ulonglong2*)s_mask;
    for (int i = tid; i < KPRE * NWORDS / 2; i += 1024) sm2[i] = gm2[i];
    __syncthreads();

    if (tid == 0) {
        u64 remv[NWORDS];
        #pragma unroll
        for (int k = 0; k < NWORDS; ++k) remv[k] = 0ull;
        int kept = 0;
        #pragma unroll
        for (int w = 0; w < NWORDS; ++w) {
            if (kept >= KPOST) break;
            const u64 valid = (w == NWORDS - 1)
                ? ((1ull << (KPRE - 64 * (NWORDS - 1))) - 1ull) : ~0ull;
            u64 avail = (~remv[w]) & valid;
            while (avail) {
                int bit = __ffsll((long long)avail) - 1;
                int i = w * 64 + bit;
                s_list[kept++] = i;
                if (kept == KPOST) break;
                const ulonglong2* row = (const ulonglong2*)&s_mask[i * NWORDS];
                switch (w >> 1) {
                case 0: { ulonglong2 v = row[0]; remv[0]  |= v.x; remv[1]  |= v.y; }
                case 1: { ulonglong2 v = row[1]; remv[2]  |= v.x; remv[3]  |= v.y; }
                case 2: { ulonglong2 v = row[2]; remv[4]  |= v.x; remv[5]  |= v.y; }
                case 3: { ulonglong2 v = row[3]; remv[6]  |= v.x; remv[7]  |= v.y; }
                case 4: { ulonglong2 v = row[4]; remv[8]  |= v.x; remv[9]  |= v.y; }
                case 5: { ulonglong2 v = row[5]; remv[10] |= v.x; remv[11] |= v.y; }
                case 6: { ulonglong2 v = row[6]; remv[12] |= v.x; remv[13] |= v.y; }
                case 7: { ulonglong2 v = row[7]; remv[14] |= v.x; remv[15] |= v.y; }
                }
                u64 high = (bit == 63) ? 0ull : (~0ull << (bit + 1));
                avail = (~remv[w]) & valid & high;
            }
        }
        s_kept = kept;
    }
    __syncthreads();

    const int kept = s_kept;
    float* ob = out + (size_t)b * KPOST * 5;
    for (int r = tid; r < KPOST; r += 1024) {
        if (r < kept) {
            int i = s_list[r];
            float4 bx = g_boxes[b][i];
            float  sc = g_scores[b][i];
            ob[r * 5 + 0] = bx.x;
            ob[r * 5 + 1] = bx.y;
            ob[r * 5 + 2] = bx.z;
            ob[r * 5 + 3] = bx.w;
            ob[r * 5 + 4] = sc;
        } else {
            ob[r * 5 + 0] = 0.0f;
            ob[r * 5 + 1] = 0.0f;
            ob[r * 5 + 2] = 0.0f;
            ob[r * 5 + 3] = 0.0f;
            ob[r * 5 + 4] = 0.0f;
        }
    }
}

// =============================================================================
extern "C" void kernel_launch(void* const* d_in, const int* in_sizes, int n_in,
                              void* d_out, int out_size)
{
    const float* logits  = (const float*)d_in[0];
    const float* deltas  = (const float*)d_in[1];
    const float* anchors = (const float*)d_in[2];
    const int*   p_ih    = (const int*)d_in[3];
    const int*   p_iw    = (const int*)d_in[4];

    cudaFuncSetAttribute(select_fused_kernel,
                         cudaFuncAttributeMaxDynamicSharedMemorySize,
                         CANDCAP * (int)sizeof(u64));     // 32 KB (== NBINS*4)
    cudaFuncSetAttribute(nms_scan_out_kernel,
                         cudaFuncAttributeMaxDynamicSharedMemorySize,
                         KPRE * NWORDS * (int)sizeof(u64));

    select_fused_kernel<<<dim3(NQ, BS), 1024, CANDCAP * sizeof(u64)>>>(
        logits, deltas, anchors, p_ih, p_iw);
    nms_mask_kernel<<<dim3(NWORDS * (NWORDS + 1) / 2, BS), 64>>>();
    nms_scan_out_kernel<<<BS, 1024, KPRE * NWORDS * sizeof(u64)>>>((float*)d_out);
}

// round 13
// speedup vs baseline: 1.3148x; 1.2394x over previous
#include <cuda_runtime.h>
#include <cstdint>

#define BS 32
#define NANCH 90000
#define NVEC (NANCH / 4)       // 22500 float4 per batch
#define NQ 4                   // slices per batch (grid 128 <= 148 SMs: ONE wave)
#define QVEC (NVEC / NQ)       // 5625
#define KPRE 1000
#define KPOST 300
#define NWORDS 16              // 16*64 = 1024 >= 1000
#define NMS_THR 0.7f

#define HBITS 12
#define NBINS (1 << HBITS)     // 4096
#define HSHIFT (32 - HBITS)    // 20
#define BPT (NBINS / 1024)     // 4 bins per thread
#define QCAP 4096
#define CANDCAP 4096

typedef unsigned long long u64;

// ---------------- scratch (static device globals; no allocation) ----------------
__device__ unsigned g_hist4[BS][NQ][NBINS];            // overwritten each run
__device__ unsigned g_qcnt[BS][NQ];
__device__ u64      g_qcand[BS][NQ][QCAP];
__device__ unsigned g_sync[BS];                        // K1 election counters
__device__ float4   g_boxes[BS][KPRE];
__device__ float    g_scores[BS][KPRE];
__device__ __align__(128) u64 g_mask[BS][KPRE][NWORDS]; // lower-tri never written (stays 0)

// float -> order-preserving uint (ascending)
__device__ __forceinline__ unsigned flip_f(float f) {
    unsigned u = __float_as_uint(f);
    return (u & 0x80000000u) ? ~u : (u | 0x80000000u);
}
__device__ __forceinline__ float unflip_f(unsigned k) {
    unsigned u = (k & 0x80000000u) ? (k ^ 0x80000000u) : ~k;
    return __uint_as_float(u);
}
__device__ __forceinline__ float read_dim(const int* p) {
    int v = *p;
    if (v > 0 && v < (1 << 24)) return (float)v;
    return __int_as_float(v);
}

// CTA suffix-threshold via warp shfl: largest bin t with suffix(t) >= KPRE.
__device__ __forceinline__ void find_threshold(
    const unsigned* hist, unsigned* s_wsum, unsigned* s_wafter, unsigned* s_t,
    int tid)
{
    const int lane = tid & 31;
    const int wrp  = tid >> 5;
    const int base = tid * BPT;
    unsigned s = 0;
    #pragma unroll
    for (int k = 0; k < BPT; ++k) s += hist[base + k];

    unsigned val = s;
    #pragma unroll
    for (int off = 1; off < 32; off <<= 1) {
        unsigned v = __shfl_down_sync(0xFFFFFFFFu, val, off);
        if (lane + off < 32) val += v;
    }
    if (lane == 0) s_wsum[wrp] = val;
    __syncthreads();

    if (wrp == 0) {
        unsigned t0 = s_wsum[lane];
        unsigned v0 = t0;
        #pragma unroll
        for (int off = 1; off < 32; off <<= 1) {
            unsigned v = __shfl_down_sync(0xFFFFFFFFu, v0, off);
            if (lane + off < 32) v0 += v;
        }
        s_wafter[lane] = v0 - t0;
    }
    __syncthreads();

    unsigned mine  = val + s_wafter[wrp];
    unsigned above = mine - s;
    if (mine >= KPRE && above < KPRE) {
        unsigned acc = above;
        int t = base;
        #pragma unroll
        for (int k = BPT - 1; k >= 0; --k) {
            acc += hist[base + k];
            if (acc >= KPRE) { t = base + k; break; }
        }
        *s_t = (unsigned)t;
    }
}

// =============================================================================
// K1: per-slice histogram + local gather; last slice-CTA per batch elected to
// do global select. grid (NQ, BS) = 128 CTAs (one wave), 1024 threads.
// =============================================================================
extern __shared__ unsigned s_dynA[];   // 32 KB: hist u32[NBINS] (16 KB) / cand u64[CANDCAP]

__global__ __launch_bounds__(1024, 2) void select_fused_kernel(
    const float* __restrict__ logits,
    const float* __restrict__ deltas,
    const float* __restrict__ anchors,
    const int* __restrict__ p_ih,
    const int* __restrict__ p_iw)
{
    const int b   = blockIdx.y;
    const int q   = blockIdx.x;
    const int tid = threadIdx.x;

    unsigned* hist = s_dynA;
    u64*      cand = (u64*)s_dynA;
    __shared__ unsigned s_wsum[32];
    __shared__ unsigned s_wafter[32];
    __shared__ unsigned s_t;
    __shared__ unsigned s_cnt;
    __shared__ int s_last;

    const float4* lg4 = (const float4*)(logits + (size_t)b * NANCH);
    const int v0 = q * QVEC;
    const int v1 = v0 + QVEC;

    for (int i = tid; i < NBINS; i += 1024) hist[i] = 0u;
    if (tid == 0) s_cnt = 0u;
    __syncthreads();

    // ---- sweep 1: histogram ----
    for (int i = v0 + tid; i < v1; i += 1024) {
        float4 v = lg4[i];
        atomicAdd(&hist[flip_f(v.x) >> HSHIFT], 1u);
        atomicAdd(&hist[flip_f(v.y) >> HSHIFT], 1u);
        atomicAdd(&hist[flip_f(v.z) >> HSHIFT], 1u);
        atomicAdd(&hist[flip_f(v.w) >> HSHIFT], 1u);
    }
    __syncthreads();

    // ---- write hist slice ----
    for (int i = tid; i < NBINS; i += 1024) g_hist4[b][q][i] = hist[i];

    // ---- local threshold ----
    find_threshold(hist, s_wsum, s_wafter, &s_t, tid);
    __syncthreads();
    const unsigned tq = s_t;

    // ---- sweep 2: gather local candidates ----
    for (int i = v0 + tid; i < v1; i += 1024) {
        float4 v = lg4[i];
        unsigned k0 = flip_f(v.x);
        unsigned k1 = flip_f(v.y);
        unsigned k2 = flip_f(v.z);
        unsigned k3 = flip_f(v.w);
        const int i0 = 4 * i;
        if ((k0 >> HSHIFT) >= tq) {
            unsigned p = atomicAdd(&s_cnt, 1u);
            if (p < QCAP) g_qcand[b][q][p] = ((u64)k0 << 32) | (unsigned)(~(unsigned)(i0));
        }
        if ((k1 >> HSHIFT) >= tq) {
            unsigned p = atomicAdd(&s_cnt, 1u);
            if (p < QCAP) g_qcand[b][q][p] = ((u64)k1 << 32) | (unsigned)(~(unsigned)(i0 + 1));
        }
        if ((k2 >> HSHIFT) >= tq) {
            unsigned p = atomicAdd(&s_cnt, 1u);
            if (p < QCAP) g_qcand[b][q][p] = ((u64)k2 << 32) | (unsigned)(~(unsigned)(i0 + 2));
        }
        if ((k3 >> HSHIFT) >= tq) {
            unsigned p = atomicAdd(&s_cnt, 1u);
            if (p < QCAP) g_qcand[b][q][p] = ((u64)k3 << 32) | (unsigned)(~(unsigned)(i0 + 3));
        }
    }
    __syncthreads();
    if (tid == 0) {
        g_qcnt[b][q] = min(s_cnt, (unsigned)QCAP);
        __threadfence();
        unsigned old = atomicAdd(&g_sync[b], 1u);
        s_last = (old == NQ - 1);
        if (s_last) g_sync[b] = 0u;
    }
    __syncthreads();
    if (!s_last) return;

    // =================== global select (elected CTA only) ===================
    __threadfence();
    if (tid == 0) s_cnt = 0u;

    for (int i = tid; i < NBINS; i += 1024) {
        unsigned s = 0;
        #pragma unroll
        for (int qq = 0; qq < NQ; ++qq) s += g_hist4[b][qq][i];
        hist[i] = s;
    }
    __syncthreads();

    find_threshold(hist, s_wsum, s_wafter, &s_t, tid);
    __syncthreads();
    const unsigned t = s_t;
    __syncthreads();            // all hist reads done before aliasing to cand

    #pragma unroll
    for (int qq = 0; qq < NQ; ++qq) {
        const int nq = (int)g_qcnt[b][qq];
        for (int i = tid; i < nq; i += 1024) {
            u64 comp = g_qcand[b][qq][i];
            if (((unsigned)(comp >> 32) >> HSHIFT) >= t) {
                unsigned p = atomicAdd(&s_cnt, 1u);
                if (p < CANDCAP) cand[p] = comp;
            }
        }
    }
    __syncthreads();

    const int n = min((int)s_cnt, CANDCAP);
    const int S = (n <= 2048) ? 2048 : CANDCAP;
    for (int i = n + tid; i < S; i += 1024) cand[i] = 0ull;

    // ---- bitonic sort desc; full barrier only around cross-warp strides ----
    int prev_big = 1;
    for (int size = 2; size <= S; size <<= 1) {
        for (int stride = size >> 1; stride > 0; stride >>= 1) {
            const int big = (stride >= 32);
            if (big || prev_big) __syncthreads(); else __syncwarp();
            for (int k = tid; k < (S >> 1); k += 1024) {
                int i = 2 * k - (k & (stride - 1));
                int j = i + stride;
                u64 a = cand[i];
                u64 c = cand[j];
                bool desc = ((i & size) == 0);
                if ((a < c) == desc) { cand[i] = c; cand[j] = a; }
            }
            prev_big = big;
        }
    }
    __syncthreads();

    // ---- decode + clip top-1000 ----
    const float fw = read_dim(p_iw);
    const float fh = read_dim(p_ih);
    if (tid < KPRE) {
        u64 comp = cand[tid];
        unsigned idx = ~(unsigned)(comp & 0xFFFFFFFFull);
        unsigned key = (unsigned)(comp >> 32);
        float logit = unflip_f(key);
        float score = 1.0f / (1.0f + expf(-logit));

        float4 d = ((const float4*)deltas)[(size_t)b * NANCH + idx];
        float4 a = ((const float4*)anchors)[idx];
        float aw  = a.z - a.x;
        float ah  = a.w - a.y;
        float acx = a.x + 0.5f * aw;
        float acy = a.y + 0.5f * ah;
        float cx = d.x * aw + acx;
        float cy = d.y * ah + acy;
        float w  = expf(d.z) * aw;
        float h  = expf(d.w) * ah;
        float x1 = fminf(fmaxf(cx - 0.5f * w, 0.0f), fw);
        float y1 = fminf(fmaxf(cy - 0.5f * h, 0.0f), fh);
        float x2 = fminf(fmaxf(cx + 0.5f * w, 0.0f), fw);
        float y2 = fminf(fmaxf(cy + 0.5f * h, 0.0f), fh);
        g_boxes[b][tid]  = make_float4(x1, y1, x2, y2);
        g_scores[b][tid] = score;
    }
}

// =============================================================================
// K2: IoU bitmask, upper-triangular blocks, divide-free fast path with exact
//     fallback near the decision boundary. grid (136, BS), 64 threads.
// =============================================================================
__global__ __launch_bounds__(64) void nms_mask_kernel()
{
    const int b = blockIdx.y;
    int p = blockIdx.x;
    int rb = 0, rem = NWORDS;
    while (p >= rem) { p -= rem; ++rb; --rem; }
    const int cb = rb + p;
    const int i  = rb * 64 + threadIdx.x;

    __shared__ float4 cbox[64];
    __shared__ float  carea[64];
    const int cbase = cb * 64;
    const int ncol  = min(64, KPRE - cbase);
    if (threadIdx.x < ncol) {
        float4 bx = g_boxes[b][cbase + threadIdx.x];
        cbox[threadIdx.x]  = bx;
        carea[threadIdx.x] = (bx.z - bx.x) * (bx.w - bx.y);
    }
    __syncthreads();
    if (i >= KPRE) return;

    u64 bits = 0ull;
    float4 bi = g_boxes[b][i];
    float  ai = (bi.z - bi.x) * (bi.w - bi.y);
    const int j0 = (i >= cbase) ? (i - cbase + 1) : 0;
    for (int j = j0; j < ncol; ++j) {
        float4 bj = cbox[j];
        float lx = fmaxf(bi.x, bj.x);
        float ly = fmaxf(bi.y, bj.y);
        float rx = fminf(bi.z, bj.z);
        float ry = fminf(bi.w, bj.w);
        float w  = fmaxf(rx - lx, 0.0f);
        float h  = fmaxf(ry - ly, 0.0f);
        float inter = w * h;
        float u = ai + carea[j] - inter + 1e-12f;
        float d = inter - NMS_THR * u;
        bool sup = d > 0.0f;
        if (fabsf(d) <= 1e-4f * u)
            sup = (inter / u) > NMS_THR;
        if (sup) bits |= (1ull << j);
    }
    g_mask[b][i][cb] = bits;
}

// =============================================================================
// K3: sequential greedy scan (R7 algorithm), register-resident removal mask,
//     LDS.128 row loads, Duff-trimmed OR. grid (BS), 1024 threads, 128 KB smem.
// =============================================================================
extern __shared__ u64 s_mask[];   // KPRE*NWORDS u64 = 128 KB

__global__ __launch_bounds__(1024) void nms_scan_out_kernel(float* __restrict__ out)
{
    const int b   = blockIdx.x;
    const int tid = threadIdx.x;

    __shared__ int s_list[KPOST];
    __shared__ int s_kept;

    const ulonglong2* gm2 = (const ulonglong2*)&g_mask[b][0][0];
    ulonglong2* sm2 = (ulonglong2*)s_mask;
    for (int i = tid; i < KPRE * NWORDS / 2; i += 1024) sm2[i] = gm2[i];
    __syncthreads();

    if (tid == 0) {
        u64 remv[NWORDS];
        #pragma unroll
        for (int k = 0; k < NWORDS; ++k) remv[k] = 0ull;
        int kept = 0;
        #pragma unroll
        for (int w = 0; w < NWORDS; ++w) {
            if (kept >= KPOST) break;
            const u64 valid = (w == NWORDS - 1)
                ? ((1ull << (KPRE - 64 * (NWORDS - 1))) - 1ull) : ~0ull;
            u64 avail = (~remv[w]) & valid;
            while (avail) {
                int bit = __ffsll((long long)avail) - 1;
                int i = w * 64 + bit;
                s_list[kept++] = i;
                if (kept == KPOST) break;
                const ulonglong2* row = (const ulonglong2*)&s_mask[i * NWORDS];
                switch (w >> 1) {
                case 0: { ulonglong2 v = row[0]; remv[0]  |= v.x; remv[1]  |= v.y; }
                case 1: { ulonglong2 v = row[1]; remv[2]  |= v.x; remv[3]  |= v.y; }
                case 2: { ulonglong2 v = row[2]; remv[4]  |= v.x; remv[5]  |= v.y; }
                case 3: { ulonglong2 v = row[3]; remv[6]  |= v.x; remv[7]  |= v.y; }
                case 4: { ulonglong2 v = row[4]; remv[8]  |= v.x; remv[9]  |= v.y; }
                case 5: { ulonglong2 v = row[5]; remv[10] |= v.x; remv[11] |= v.y; }
                case 6: { ulonglong2 v = row[6]; remv[12] |= v.x; remv[13] |= v.y; }
                case 7: { ulonglong2 v = row[7]; remv[14] |= v.x; remv[15] |= v.y; }
                }
                u64 high = (bit == 63) ? 0ull : (~0ull << (bit + 1));
                avail = (~remv[w]) & valid & high;
            }
        }
        s_kept = kept;
    }
    __syncthreads();

    const int kept = s_kept;
    float* ob = out + (size_t)b * KPOST * 5;
    for (int r = tid; r < KPOST; r += 1024) {
        if (r < kept) {
            int i = s_list[r];
            float4 bx = g_boxes[b][i];
            float  sc = g_scores[b][i];
            ob[r * 5 + 0] = bx.x;
            ob[r * 5 + 1] = bx.y;
            ob[r * 5 + 2] = bx.z;
            ob[r * 5 + 3] = bx.w;
            ob[r * 5 + 4] = sc;
        } else {
            ob[r * 5 + 0] = 0.0f;
            ob[r * 5 + 1] = 0.0f;
            ob[r * 5 + 2] = 0.0f;
            ob[r * 5 + 3] = 0.0f;
            ob[r * 5 + 4] = 0.0f;
        }
    }
}

// =============================================================================
extern "C" void kernel_launch(void* const* d_in, const int* in_sizes, int n_in,
                              void* d_out, int out_size)
{
    const float* logits  = (const float*)d_in[0];
    const float* deltas  = (const float*)d_in[1];
    const float* anchors = (const float*)d_in[2];
    const int*   p_ih    = (const int*)d_in[3];
    const int*   p_iw    = (const int*)d_in[4];

    cudaFuncSetAttribute(select_fused_kernel,
                         cudaFuncAttributeMaxDynamicSharedMemorySize,
                         CANDCAP * (int)sizeof(u64));     // 32 KB
    cudaFuncSetAttribute(nms_scan_out_kernel,
                         cudaFuncAttributeMaxDynamicSharedMemorySize,
                         KPRE * NWORDS * (int)sizeof(u64));

    select_fused_kernel<<<dim3(NQ, BS), 1024, CANDCAP * sizeof(u64)>>>(
        logits, deltas, anchors, p_ih, p_iw);
    nms_mask_kernel<<<dim3(NWORDS * (NWORDS + 1) / 2, BS), 64>>>();
    nms_scan_out_kernel<<<BS, 1024, KPRE * NWORDS * sizeof(u64)>>>((float*)d_out);
}

// round 14
// speedup vs baseline: 1.3153x; 1.0004x over previous
#include <cuda_runtime.h>
#include <cstdint>

#define BS 32
#define NANCH 90000
#define NVEC (NANCH / 4)       // 22500 float4 per batch
#define NQ 4                   // slices per batch (grid 128 <= 148 SMs: ONE wave)
#define QVEC (NVEC / NQ)       // 5625
#define KPRE 1000
#define KPOST 300
#define NWORDS 16              // 16*64 = 1024 >= 1000
#define NMS_THR 0.7f

#define HBITS 12
#define NBINS (1 << HBITS)     // 4096
#define HSHIFT (32 - HBITS)    // 20
#define BPT (NBINS / 1024)     // 4 bins per thread
#define QCAP 4096
#define CANDCAP 4096

typedef unsigned long long u64;

// ---------------- scratch (static device globals; no allocation) ----------------
__device__ unsigned g_hist4[BS][NQ][NBINS];            // overwritten each run
__device__ unsigned g_qcnt[BS][NQ];
__device__ u64      g_qcand[BS][NQ][QCAP];
__device__ unsigned g_sync[BS];                        // K1 election counters
__device__ float4   g_boxes[BS][KPRE];
__device__ float    g_scores[BS][KPRE];
__device__ __align__(128) u64 g_mask[BS][KPRE][NWORDS]; // lower-tri never written/read

// float -> order-preserving uint (ascending)
__device__ __forceinline__ unsigned flip_f(float f) {
    unsigned u = __float_as_uint(f);
    return (u & 0x80000000u) ? ~u : (u | 0x80000000u);
}
__device__ __forceinline__ float unflip_f(unsigned k) {
    unsigned u = (k & 0x80000000u) ? (k ^ 0x80000000u) : ~k;
    return __uint_as_float(u);
}
__device__ __forceinline__ float read_dim(const int* p) {
    int v = *p;
    if (v > 0 && v < (1 << 24)) return (float)v;
    return __int_as_float(v);
}

// CTA suffix-threshold via warp shfl: largest bin t with suffix(t) >= KPRE.
__device__ __forceinline__ void find_threshold(
    const unsigned* hist, unsigned* s_wsum, unsigned* s_wafter, unsigned* s_t,
    int tid)
{
    const int lane = tid & 31;
    const int wrp  = tid >> 5;
    const int base = tid * BPT;
    unsigned s = 0;
    #pragma unroll
    for (int k = 0; k < BPT; ++k) s += hist[base + k];

    unsigned val = s;
    #pragma unroll
    for (int off = 1; off < 32; off <<= 1) {
        unsigned v = __shfl_down_sync(0xFFFFFFFFu, val, off);
        if (lane + off < 32) val += v;
    }
    if (lane == 0) s_wsum[wrp] = val;
    __syncthreads();

    if (wrp == 0) {
        unsigned t0 = s_wsum[lane];
        unsigned v0 = t0;
        #pragma unroll
        for (int off = 1; off < 32; off <<= 1) {
            unsigned v = __shfl_down_sync(0xFFFFFFFFu, v0, off);
            if (lane + off < 32) v0 += v;
        }
        s_wafter[lane] = v0 - t0;
    }
    __syncthreads();

    unsigned mine  = val + s_wafter[wrp];
    unsigned above = mine - s;
    if (mine >= KPRE && above < KPRE) {
        unsigned acc = above;
        int t = base;
        #pragma unroll
        for (int k = BPT - 1; k >= 0; --k) {
            acc += hist[base + k];
            if (acc >= KPRE) { t = base + k; break; }
        }
        *s_t = (unsigned)t;
    }
}

// =============================================================================
// K1: per-slice histogram + local gather; last slice-CTA per batch elected to
// do global select. grid (NQ, BS) = 128 CTAs (one wave), 1024 threads.
// =============================================================================
extern __shared__ unsigned s_dynA[];   // 32 KB: hist u32[NBINS] / cand u64[CANDCAP]

__global__ __launch_bounds__(1024, 2) void select_fused_kernel(
    const float* __restrict__ logits,
    const float* __restrict__ deltas,
    const float* __restrict__ anchors,
    const int* __restrict__ p_ih,
    const int* __restrict__ p_iw)
{
    const int b   = blockIdx.y;
    const int q   = blockIdx.x;
    const int tid = threadIdx.x;

    unsigned* hist = s_dynA;
    u64*      cand = (u64*)s_dynA;
    __shared__ unsigned s_wsum[32];
    __shared__ unsigned s_wafter[32];
    __shared__ unsigned s_t;
    __shared__ unsigned s_cnt;
    __shared__ int s_last;

    const float4* lg4 = (const float4*)(logits + (size_t)b * NANCH);
    const int v0 = q * QVEC;
    const int v1 = v0 + QVEC;

    for (int i = tid; i < NBINS; i += 1024) hist[i] = 0u;
    if (tid == 0) s_cnt = 0u;
    __syncthreads();

    // ---- sweep 1: histogram ----
    for (int i = v0 + tid; i < v1; i += 1024) {
        float4 v = lg4[i];
        atomicAdd(&hist[flip_f(v.x) >> HSHIFT], 1u);
        atomicAdd(&hist[flip_f(v.y) >> HSHIFT], 1u);
        atomicAdd(&hist[flip_f(v.z) >> HSHIFT], 1u);
        atomicAdd(&hist[flip_f(v.w) >> HSHIFT], 1u);
    }
    __syncthreads();

    // ---- write hist slice ----
    for (int i = tid; i < NBINS; i += 1024) g_hist4[b][q][i] = hist[i];

    // ---- local threshold ----
    find_threshold(hist, s_wsum, s_wafter, &s_t, tid);
    __syncthreads();
    const unsigned tq = s_t;

    // ---- sweep 2: gather local candidates ----
    for (int i = v0 + tid; i < v1; i += 1024) {
        float4 v = lg4[i];
        unsigned k0 = flip_f(v.x);
        unsigned k1 = flip_f(v.y);
        unsigned k2 = flip_f(v.z);
        unsigned k3 = flip_f(v.w);
        const int i0 = 4 * i;
        if ((k0 >> HSHIFT) >= tq) {
            unsigned p = atomicAdd(&s_cnt, 1u);
            if (p < QCAP) g_qcand[b][q][p] = ((u64)k0 << 32) | (unsigned)(~(unsigned)(i0));
        }
        if ((k1 >> HSHIFT) >= tq) {
            unsigned p = atomicAdd(&s_cnt, 1u);
            if (p < QCAP) g_qcand[b][q][p] = ((u64)k1 << 32) | (unsigned)(~(unsigned)(i0 + 1));
        }
        if ((k2 >> HSHIFT) >= tq) {
            unsigned p = atomicAdd(&s_cnt, 1u);
            if (p < QCAP) g_qcand[b][q][p] = ((u64)k2 << 32) | (unsigned)(~(unsigned)(i0 + 2));
        }
        if ((k3 >> HSHIFT) >= tq) {
            unsigned p = atomicAdd(&s_cnt, 1u);
            if (p < QCAP) g_qcand[b][q][p] = ((u64)k3 << 32) | (unsigned)(~(unsigned)(i0 + 3));
        }
    }
    __syncthreads();
    if (tid == 0) {
        g_qcnt[b][q] = min(s_cnt, (unsigned)QCAP);
        __threadfence();
        unsigned old = atomicAdd(&g_sync[b], 1u);
        s_last = (old == NQ - 1);
        if (s_last) g_sync[b] = 0u;
    }
    __syncthreads();
    if (!s_last) return;

    // =================== global select (elected CTA only) ===================
    __threadfence();
    if (tid == 0) s_cnt = 0u;

    for (int i = tid; i < NBINS; i += 1024) {
        unsigned s = 0;
        #pragma unroll
        for (int qq = 0; qq < NQ; ++qq) s += g_hist4[b][qq][i];
        hist[i] = s;
    }
    __syncthreads();

    find_threshold(hist, s_wsum, s_wafter, &s_t, tid);
    __syncthreads();
    const unsigned t = s_t;
    __syncthreads();            // all hist reads done before aliasing to cand

    #pragma unroll
    for (int qq = 0; qq < NQ; ++qq) {
        const int nq = (int)g_qcnt[b][qq];
        for (int i = tid; i < nq; i += 1024) {
            u64 comp = g_qcand[b][qq][i];
            if (((unsigned)(comp >> 32) >> HSHIFT) >= t) {
                unsigned p = atomicAdd(&s_cnt, 1u);
                if (p < CANDCAP) cand[p] = comp;
            }
        }
    }
    __syncthreads();

    const int n = min((int)s_cnt, CANDCAP);
    const int S = (n <= 2048) ? 2048 : CANDCAP;
    for (int i = n + tid; i < S; i += 1024) cand[i] = 0ull;

    // ---- bitonic sort desc; full barrier only around cross-warp strides ----
    int prev_big = 1;
    for (int size = 2; size <= S; size <<= 1) {
        for (int stride = size >> 1; stride > 0; stride >>= 1) {
            const int big = (stride >= 32);
            if (big || prev_big) __syncthreads(); else __syncwarp();
            for (int k = tid; k < (S >> 1); k += 1024) {
                int i = 2 * k - (k & (stride - 1));
                int j = i + stride;
                u64 a = cand[i];
                u64 c = cand[j];
                bool desc = ((i & size) == 0);
                if ((a < c) == desc) { cand[i] = c; cand[j] = a; }
            }
            prev_big = big;
        }
    }
    __syncthreads();

    // ---- decode + clip top-1000 ----
    const float fw = read_dim(p_iw);
    const float fh = read_dim(p_ih);
    if (tid < KPRE) {
        u64 comp = cand[tid];
        unsigned idx = ~(unsigned)(comp & 0xFFFFFFFFull);
        unsigned key = (unsigned)(comp >> 32);
        float logit = unflip_f(key);
        float score = 1.0f / (1.0f + expf(-logit));

        float4 d = ((const float4*)deltas)[(size_t)b * NANCH + idx];
        float4 a = ((const float4*)anchors)[idx];
        float aw  = a.z - a.x;
        float ah  = a.w - a.y;
        float acx = a.x + 0.5f * aw;
        float acy = a.y + 0.5f * ah;
        float cx = d.x * aw + acx;
        float cy = d.y * ah + acy;
        float w  = expf(d.z) * aw;
        float h  = expf(d.w) * ah;
        float x1 = fminf(fmaxf(cx - 0.5f * w, 0.0f), fw);
        float y1 = fminf(fmaxf(cy - 0.5f * h, 0.0f), fh);
        float x2 = fminf(fmaxf(cx + 0.5f * w, 0.0f), fw);
        float y2 = fminf(fmaxf(cy + 0.5f * h, 0.0f), fh);
        g_boxes[b][tid]  = make_float4(x1, y1, x2, y2);
        g_scores[b][tid] = score;
    }
}

// =============================================================================
// K2: IoU bitmask, upper-triangular blocks, divide-free fast path with exact
//     fallback near the decision boundary. grid (136, BS), 64 threads.
// =============================================================================
__global__ __launch_bounds__(64) void nms_mask_kernel()
{
    const int b = blockIdx.y;
    int p = blockIdx.x;
    int rb = 0, rem = NWORDS;
    while (p >= rem) { p -= rem; ++rb; --rem; }
    const int cb = rb + p;
    const int i  = rb * 64 + threadIdx.x;

    __shared__ float4 cbox[64];
    __shared__ float  carea[64];
    const int cbase = cb * 64;
    const int ncol  = min(64, KPRE - cbase);
    if (threadIdx.x < ncol) {
        float4 bx = g_boxes[b][cbase + threadIdx.x];
        cbox[threadIdx.x]  = bx;
        carea[threadIdx.x] = (bx.z - bx.x) * (bx.w - bx.y);
    }
    __syncthreads();
    if (i >= KPRE) return;

    u64 bits = 0ull;
    float4 bi = g_boxes[b][i];
    float  ai = (bi.z - bi.x) * (bi.w - bi.y);
    const int j0 = (i >= cbase) ? (i - cbase + 1) : 0;
    for (int j = j0; j < ncol; ++j) {
        float4 bj = cbox[j];
        float lx = fmaxf(bi.x, bj.x);
        float ly = fmaxf(bi.y, bj.y);
        float rx = fminf(bi.z, bj.z);
        float ry = fminf(bi.w, bj.w);
        float w  = fmaxf(rx - lx, 0.0f);
        float h  = fmaxf(ry - ly, 0.0f);
        float inter = w * h;
        float u = ai + carea[j] - inter + 1e-12f;
        float d = inter - NMS_THR * u;
        bool sup = d > 0.0f;
        if (fabsf(d) <= 1e-4f * u)
            sup = (inter / u) > NMS_THR;
        if (sup) bits |= (1ull << j);
    }
    g_mask[b][i][cb] = bits;
}

// =============================================================================
// K3: single-thread greedy scan with SINGLE-WORD removal mask.
// Inner loop per kept box: 1 LDS.64 + AND/FFS (minimal critical path).
// Word transitions: pipelined 4-way OR over previously-kept rows' new word.
// Triangular preload: row i only needs words >= i/64.
// =============================================================================
extern __shared__ u64 s_mask[];   // KPRE*NWORDS u64 = 128 KB (upper-tri valid)

__global__ __launch_bounds__(1024) void nms_scan_out_kernel(float* __restrict__ out)
{
    const int b   = blockIdx.x;
    const int tid = threadIdx.x;

    __shared__ int s_list[KPOST];
    __shared__ int s_kept;

    // triangular preload: row i pair p (words 2p,2p+1) needed only if 2p+1 >= i/64
    const ulonglong2* gm2 = (const ulonglong2*)&g_mask[b][0][0];
    ulonglong2* sm2 = (ulonglong2*)s_mask;
    for (int idx = tid; idx < KPRE * (NWORDS / 2); idx += 1024) {
        int i = idx >> 3;
        int p = idx & 7;
        if (2 * p + 1 >= (i >> 6)) sm2[idx] = gm2[idx];
    }
    __syncthreads();

    if (tid == 0) {
        int kept = 0;
        #pragma unroll 1
        for (int w = 0; w < NWORDS; ++w) {
            if (kept >= KPOST) break;
            const u64 valid = (w == NWORDS - 1)
                ? ((1ull << (KPRE - 64 * (NWORDS - 1))) - 1ull) : ~0ull;

            // word transition: OR previously-kept rows' word w (pipelined)
            u64 a0 = 0ull, a1 = 0ull, a2 = 0ull, a3 = 0ull;
            int k = 0;
            for (; k + 4 <= kept; k += 4) {
                a0 |= s_mask[s_list[k + 0] * NWORDS + w];
                a1 |= s_mask[s_list[k + 1] * NWORDS + w];
                a2 |= s_mask[s_list[k + 2] * NWORDS + w];
                a3 |= s_mask[s_list[k + 3] * NWORDS + w];
            }
            for (; k < kept; ++k)
                a0 |= s_mask[s_list[k] * NWORDS + w];
            u64 avail = ~((a0 | a1) | (a2 | a3)) & valid;

            // serial scan within word w: 1 dependent LDS per kept box
            while (avail) {
                int bit = __ffsll((long long)avail) - 1;
                int i = w * 64 + bit;
                s_list[kept++] = i;
                if (kept == KPOST) break;
                u64 rw = s_mask[i * NWORDS + w];
                u64 high = (bit == 63) ? 0ull : (~0ull << (bit + 1));
                avail = avail & ~rw & high;
            }
        }
        s_kept = kept;
    }
    __syncthreads();

    const int kept = s_kept;
    float* ob = out + (size_t)b * KPOST * 5;
    for (int r = tid; r < KPOST; r += 1024) {
        if (r < kept) {
            int i = s_list[r];
            float4 bx = g_boxes[b][i];
            float  sc = g_scores[b][i];
            ob[r * 5 + 0] = bx.x;
            ob[r * 5 + 1] = bx.y;
            ob[r * 5 + 2] = bx.z;
            ob[r * 5 + 3] = bx.w;
            ob[r * 5 + 4] = sc;
        } else {
            ob[r * 5 + 0] = 0.0f;
            ob[r * 5 + 1] = 0.0f;
            ob[r * 5 + 2] = 0.0f;
            ob[r * 5 + 3] = 0.0f;
            ob[r * 5 + 4] = 0.0f;
        }
    }
}

// =============================================================================
extern "C" void kernel_launch(void* const* d_in, const int* in_sizes, int n_in,
                              void* d_out, int out_size)
{
    const float* logits  = (const float*)d_in[0];
    const float* deltas  = (const float*)d_in[1];
    const float* anchors = (const float*)d_in[2];
    const int*   p_ih    = (const int*)d_in[3];
    const int*   p_iw    = (const int*)d_in[4];

    cudaFuncSetAttribute(select_fused_kernel,
                         cudaFuncAttributeMaxDynamicSharedMemorySize,
                         CANDCAP * (int)sizeof(u64));     // 32 KB
    cudaFuncSetAttribute(nms_scan_out_kernel,
                         cudaFuncAttributeMaxDynamicSharedMemorySize,
                         KPRE * NWORDS * (int)sizeof(u64));

    select_fused_kernel<<<dim3(NQ, BS), 1024, CANDCAP * sizeof(u64)>>>(
        logits, deltas, anchors, p_ih, p_iw);
    nms_mask_kernel<<<dim3(NWORDS * (NWORDS + 1) / 2, BS), 64>>>();
    nms_scan_out_kernel<<<BS, 1024, KPRE * NWORDS * sizeof(u64)>>>((float*)d_out);
}